// round 6
// baseline (speedup 1.0000x reference)
#include <cuda_runtime.h>
#include <cuda_bf16.h>
#include <cstdint>

// Problem constants
#define Bn   16
#define Nn   4096
#define Mn   1024
#define C1n  128
#define C2n  256
#define CINn 384
#define H1n  256
#define H2n  128

// ---------------- helpers ----------------
__device__ __forceinline__ uint32_t smem_u32(const void* p) {
    uint32_t a;
    asm("{ .reg .u64 t; cvta.to.shared.u64 t, %1; cvt.u32.u64 %0, t; }" : "=r"(a) : "l"(p));
    return a;
}
__device__ __forceinline__ void ldsm4(uint32_t* r, uint32_t addr) {
    asm volatile("ldmatrix.sync.aligned.m8n8.x4.shared.b16 {%0,%1,%2,%3}, [%4];"
        : "=r"(r[0]), "=r"(r[1]), "=r"(r[2]), "=r"(r[3]) : "r"(addr));
}
__device__ __forceinline__ void ldsm4t(uint32_t* r, uint32_t addr) {
    asm volatile("ldmatrix.sync.aligned.m8n8.x4.trans.shared.b16 {%0,%1,%2,%3}, [%4];"
        : "=r"(r[0]), "=r"(r[1]), "=r"(r[2]), "=r"(r[3]) : "r"(addr));
}
__device__ __forceinline__ void mma_bf16(float* d, const uint32_t* a, const uint32_t* b) {
    asm volatile("mma.sync.aligned.m16n8k16.row.col.f32.bf16.bf16.f32 "
        "{%0,%1,%2,%3}, {%4,%5,%6,%7}, {%8,%9}, {%0,%1,%2,%3};"
        : "+f"(d[0]), "+f"(d[1]), "+f"(d[2]), "+f"(d[3])
        : "r"(a[0]), "r"(a[1]), "r"(a[2]), "r"(a[3]), "r"(b[0]), "r"(b[1]));
}
__device__ __forceinline__ uint32_t bfhi2(float a, float b) {
    return __byte_perm(__float_as_uint(a), __float_as_uint(b), 0x7632);
}
__device__ __forceinline__ uint32_t bflo2(float a, float b) {
    const float la = a - __uint_as_float(__float_as_uint(a) & 0xFFFF0000u);
    const float lb = b - __uint_as_float(__float_as_uint(b) & 0xFFFF0000u);
    __nv_bfloat162 p = __floats2bfloat162_rn(la, lb);
    return *(uint32_t*)&p;
}

// scratch: interpolated features [B][C2][N] fp32
__device__ float g_interp[(size_t)Bn * C2n * Nn];

// paired-row address: two logical 64B rows per 144B physical row (conflict-free ldsm)
#define PR(r) (((r) >> 1) * 144 + ((r) & 1) * 64)

// ================= Kernel 1: interpolation via mma.sync =================
// CTA: 64 n x 256 c.  K = M = 1024 in 32-chunks, double-buffered.
// A [64n][32k] pitch 80; B [256c][32k] paired rows pitch 144.
#define IA(buf, part)  ((buf) * 10240 + (part) * 5120)
#define IB(buf, part)  (20480 + (buf) * 36864 + (part) * 18432)
#define IOFF_X2  94208
#define IOFF_DS  106496
#define IOFF_DEN 107520
#define ISMB     107776

__global__ __launch_bounds__(256, 2)
void interp_tc(const float* __restrict__ xyz1,
               const float* __restrict__ xyz2,
               const float* __restrict__ p2)
{
    extern __shared__ char smc[];
    const uint32_t sb = smem_u32(smc);
    float* s_x2  = (float*)(smc + IOFF_X2);
    float* s_ds  = (float*)(smc + IOFF_DS);
    float* s_den = (float*)(smc + IOFF_DEN);

    const int tid = threadIdx.x, w = tid >> 5, lane = tid & 31;
    const int b = blockIdx.y, n0 = blockIdx.x * 64;

    for (int i = tid; i < Mn * 3; i += 256)
        s_x2[i] = xyz2[(size_t)b * Mn * 3 + i];
    __syncthreads();

    const int nf = tid & 63;        // point this thread generates weights for
    const int g  = tid >> 6;        // 8-m group within 32-chunk
    const float px = xyz1[((size_t)b * Nn + n0 + nf) * 3 + 0];
    const float py = xyz1[((size_t)b * Nn + n0 + nf) * 3 + 1];
    const float pz = xyz1[((size_t)b * Nn + n0 + nf) * 3 + 2];
    float dsum = 0.f;

    const int mw = w & 1, cw = w >> 1;   // warp tile: 32 n x 64 c
    float acc[16][4];
    #pragma unroll
    for (int i = 0; i < 16; i++)
        #pragma unroll
        for (int j = 0; j < 4; j++) acc[i][j] = 0.f;

    #define FILL(ch) do {                                                          \
        const int _buf = (ch) & 1, _m0 = (ch) * 32;                                \
        float iv[8];                                                               \
        _Pragma("unroll")                                                          \
        for (int t = 0; t < 8; t++) {                                              \
            const int m = _m0 + g * 8 + t;                                         \
            const float dx = px - s_x2[m * 3 + 0];                                 \
            const float dy = py - s_x2[m * 3 + 1];                                 \
            const float dz = pz - s_x2[m * 3 + 2];                                 \
            const float d2 = fmaf(dx, dx, fmaf(dy, dy, fmaf(dz, dz, 1e-16f)));     \
            iv[t] = rsqrtf(d2);                                                    \
            dsum += iv[t];                                                         \
        }                                                                          \
        uint4 hv, lv;                                                              \
        hv.x = bfhi2(iv[0], iv[1]); hv.y = bfhi2(iv[2], iv[3]);                    \
        hv.z = bfhi2(iv[4], iv[5]); hv.w = bfhi2(iv[6], iv[7]);                    \
        lv.x = bflo2(iv[0], iv[1]); lv.y = bflo2(iv[2], iv[3]);                    \
        lv.z = bflo2(iv[4], iv[5]); lv.w = bflo2(iv[6], iv[7]);                    \
        *(uint4*)(smc + IA(_buf, 0) + nf * 80 + g * 16) = hv;                      \
        *(uint4*)(smc + IA(_buf, 1) + nf * 80 + g * 16) = lv;                      \
        _Pragma("unroll")                                                          \
        for (int it = 0; it < 8; it++) {                                           \
            const int u = tid + it * 256;                                          \
            const int c = u >> 3, q = u & 7;                                       \
            const float4 v = *(const float4*)&p2[((size_t)b * C2n + c) * Mn + _m0 + q * 4]; \
            uint2 hv2, lv2;                                                        \
            hv2.x = bfhi2(v.x, v.y); hv2.y = bfhi2(v.z, v.w);                      \
            lv2.x = bflo2(v.x, v.y); lv2.y = bflo2(v.z, v.w);                      \
            *(uint2*)(smc + IB(_buf, 0) + PR(c) + q * 8) = hv2;                    \
            *(uint2*)(smc + IB(_buf, 1) + PR(c) + q * 8) = lv2;                    \
        }                                                                          \
    } while (0)

    FILL(0);
    __syncthreads();

    for (int ch = 0; ch < 32; ch++) {
        const int buf = ch & 1;
        #pragma unroll
        for (int kk = 0; kk < 2; kk++) {
            uint32_t ah[2][4], al[2][4];
            #pragma unroll
            for (int mt = 0; mt < 2; mt++) {
                const uint32_t row = mw * 32 + mt * 16 + (lane & 15);
                const uint32_t off = row * 80 + kk * 32 + (lane >> 4) * 16;
                ldsm4(ah[mt], sb + IA(buf, 0) + off);
                ldsm4(al[mt], sb + IA(buf, 1) + off);
            }
            uint32_t bh[8][2], bl[8][2];
            #pragma unroll
            for (int cp = 0; cp < 4; cp++) {
                const uint32_t c = cw * 64 + cp * 16 + (lane >> 4) * 8 + (lane & 7);
                const uint32_t off = PR(c) + kk * 32 + ((lane >> 3) & 1) * 16;
                uint32_t r[4];
                ldsm4(r, sb + IB(buf, 0) + off);
                bh[cp * 2][0] = r[0]; bh[cp * 2][1] = r[1];
                bh[cp * 2 + 1][0] = r[2]; bh[cp * 2 + 1][1] = r[3];
                ldsm4(r, sb + IB(buf, 1) + off);
                bl[cp * 2][0] = r[0]; bl[cp * 2][1] = r[1];
                bl[cp * 2 + 1][0] = r[2]; bl[cp * 2 + 1][1] = r[3];
            }
            #pragma unroll
            for (int mt = 0; mt < 2; mt++)
                #pragma unroll
                for (int ct = 0; ct < 8; ct++) {
                    mma_bf16(acc[mt * 8 + ct], ah[mt], bh[ct]);
                    mma_bf16(acc[mt * 8 + ct], ah[mt], bl[ct]);
                    mma_bf16(acc[mt * 8 + ct], al[mt], bh[ct]);
                }
        }
        if (ch < 31) FILL(ch + 1);
        __syncthreads();
    }
    #undef FILL

    // denominator
    s_ds[tid] = dsum;
    __syncthreads();
    if (tid < 64)
        s_den[tid] = 1.0f / (s_ds[tid] + s_ds[tid + 64] + s_ds[tid + 128] + s_ds[tid + 192]);
    __syncthreads();

    // epilogue: scale and store
    #pragma unroll
    for (int mt = 0; mt < 2; mt++) {
        const int nl = mw * 32 + mt * 16 + (lane >> 2);
        const float i0 = s_den[nl], i1 = s_den[nl + 8];
        #pragma unroll
        for (int ct = 0; ct < 8; ct++) {
            const int c = cw * 64 + ct * 8 + (lane & 3) * 2;
            float* d0 = &g_interp[((size_t)b * C2n + c) * Nn + n0];
            float* d1 = &g_interp[((size_t)b * C2n + c + 1) * Nn + n0];
            const float* a = acc[mt * 8 + ct];
            d0[nl]     = a[0] * i0;
            d1[nl]     = a[1] * i0;
            d0[nl + 8] = a[2] * i1;
            d1[nl + 8] = a[3] * i1;
        }
    }
}

// ================= Kernel 2: fused 2-layer MLP via mma.sync =================
// CTA: 64 n. GEMM1: 256o x 64n x K384 (32-chunks); GEMM2: 128o x 64n x K256.
#define MW(buf, part)   ((buf) * 36864 + (part) * 18432)          // W1 chunk [256o][32k] paired
#define MH(part)        ((part) * 36864)                           // h [256k][64n] (overlays MW)
#define MX(buf, part)   (73728 + (buf) * 9216 + (part) * 4608)     // x chunk [32k][64n]
#define MW2(buf, part)  (73728 + (buf) * 18432 + (part) * 9216)    // W2 chunk [128o][32k] paired
#define MOFF_B1  110592
#define MOFF_B2  111616
#define MSMB     112128

__global__ __launch_bounds__(256, 2)
void mlp_tc(const float* __restrict__ p1,
            const float* __restrict__ W1,
            const float* __restrict__ b1,
            const float* __restrict__ W2,
            const float* __restrict__ b2,
            float* __restrict__ out)
{
    extern __shared__ char smc[];
    const uint32_t sb = smem_u32(smc);
    float* s_b1 = (float*)(smc + MOFF_B1);
    float* s_b2 = (float*)(smc + MOFF_B2);

    const int tid = threadIdx.x, w = tid >> 5, lane = tid & 31;
    const int b = blockIdx.y, n0 = blockIdx.x * 64;

    s_b1[tid] = b1[tid];
    if (tid < H2n) s_b2[tid] = b2[tid];

    const int ow = w >> 1, nw = w & 1;   // GEMM1 warp: 64 o x 32 n

    #define FILLW1(kc) do {                                                         \
        const int _buf = (kc) & 1;                                                  \
        _Pragma("unroll")                                                           \
        for (int it = 0; it < 8; it++) {                                            \
            const int u = tid + it * 256;                                           \
            const int o = u >> 3, q = u & 7;                                        \
            const float4 v = *(const float4*)&W1[(size_t)o * CINn + (kc) * 32 + q * 4]; \
            uint2 hv, lv;                                                           \
            hv.x = bfhi2(v.x, v.y); hv.y = bfhi2(v.z, v.w);                         \
            lv.x = bflo2(v.x, v.y); lv.y = bflo2(v.z, v.w);                         \
            *(uint2*)(smc + MW(_buf, 0) + PR(o) + q * 8) = hv;                      \
            *(uint2*)(smc + MW(_buf, 1) + PR(o) + q * 8) = lv;                      \
        }                                                                           \
    } while (0)

    #define FILLX(kc) do {                                                          \
        const int _buf = (kc) & 1;                                                  \
        _Pragma("unroll")                                                           \
        for (int it = 0; it < 2; it++) {                                            \
            const int u = tid + it * 256;                                           \
            const int k = u >> 4, q = u & 15;                                       \
            const int c = (kc) * 32 + k;                                            \
            const float* src = (c < C1n)                                            \
                ? &p1[((size_t)b * C1n + c) * Nn]                                   \
                : &g_interp[((size_t)b * C2n + (c - C1n)) * Nn];                    \
            const float4 v = *(const float4*)&src[n0 + q * 4];                      \
            uint2 hv, lv;                                                           \
            hv.x = bfhi2(v.x, v.y); hv.y = bfhi2(v.z, v.w);                         \
            lv.x = bflo2(v.x, v.y); lv.y = bflo2(v.z, v.w);                         \
            *(uint2*)(smc + MX(_buf, 0) + k * 144 + q * 8) = hv;                    \
            *(uint2*)(smc + MX(_buf, 1) + k * 144 + q * 8) = lv;                    \
        }                                                                           \
    } while (0)

    float acc1[16][4];
    #pragma unroll
    for (int i = 0; i < 16; i++)
        #pragma unroll
        for (int j = 0; j < 4; j++) acc1[i][j] = 0.f;

    FILLW1(0); FILLX(0);
    __syncthreads();

    for (int kc = 0; kc < 12; kc++) {
        const int buf = kc & 1;
        #pragma unroll
        for (int kk = 0; kk < 2; kk++) {
            uint32_t wh[4][4], wl[4][4];
            #pragma unroll
            for (int mi = 0; mi < 4; mi++) {
                const uint32_t o = ow * 64 + mi * 16 + (lane & 15);
                const uint32_t off = PR(o) + kk * 32 + (lane >> 4) * 16;
                ldsm4(wh[mi], sb + MW(buf, 0) + off);
                ldsm4(wl[mi], sb + MW(buf, 1) + off);
            }
            uint32_t xh[4][2], xl[4][2];
            #pragma unroll
            for (int np = 0; np < 2; np++) {
                const uint32_t row  = kk * 16 + ((lane >> 3) & 1) * 8 + (lane & 7);
                const uint32_t colb = (nw * 32 + np * 16) * 2 + (lane >> 4) * 16;
                uint32_t r[4];
                ldsm4t(r, sb + MX(buf, 0) + row * 144 + colb);
                xh[np * 2][0] = r[0]; xh[np * 2][1] = r[1];
                xh[np * 2 + 1][0] = r[2]; xh[np * 2 + 1][1] = r[3];
                ldsm4t(r, sb + MX(buf, 1) + row * 144 + colb);
                xl[np * 2][0] = r[0]; xl[np * 2][1] = r[1];
                xl[np * 2 + 1][0] = r[2]; xl[np * 2 + 1][1] = r[3];
            }
            #pragma unroll
            for (int mi = 0; mi < 4; mi++)
                #pragma unroll
                for (int ni = 0; ni < 4; ni++) {
                    mma_bf16(acc1[mi * 4 + ni], wh[mi], xh[ni]);
                    mma_bf16(acc1[mi * 4 + ni], wh[mi], xl[ni]);
                    mma_bf16(acc1[mi * 4 + ni], wl[mi], xh[ni]);
                }
        }
        if (kc < 11) { FILLW1(kc + 1); FILLX(kc + 1); }
        __syncthreads();
    }
    #undef FILLW1
    #undef FILLX

    #define FILLW2(kc) do {                                                         \
        const int _buf = (kc) & 1;                                                  \
        _Pragma("unroll")                                                           \
        for (int it = 0; it < 4; it++) {                                            \
            const int u = tid + it * 256;                                           \
            const int o = u >> 3, q = u & 7;                                        \
            const float4 v = *(const float4*)&W2[(size_t)o * H1n + (kc) * 32 + q * 4]; \
            uint2 hv, lv;                                                           \
            hv.x = bfhi2(v.x, v.y); hv.y = bfhi2(v.z, v.w);                         \
            lv.x = bflo2(v.x, v.y); lv.y = bflo2(v.z, v.w);                         \
            *(uint2*)(smc + MW2(_buf, 0) + PR(o) + q * 8) = hv;                     \
            *(uint2*)(smc + MW2(_buf, 1) + PR(o) + q * 8) = lv;                     \
        }                                                                           \
    } while (0)

    // region1 reads (W1) and region2 reads (x) are done; repurpose both
    FILLW2(0);

    // GEMM1 epilogue: relu + bias -> s_h [256 k-rows][64 n], hi/lo (overlays MW)
    #pragma unroll
    for (int mi = 0; mi < 4; mi++) {
        const int o = ow * 64 + mi * 16 + (lane >> 2);
        const float bia0 = s_b1[o], bia1 = s_b1[o + 8];
        #pragma unroll
        for (int ni = 0; ni < 4; ni++) {
            const int n = nw * 32 + ni * 8 + (lane & 3) * 2;
            const float* a = acc1[mi * 4 + ni];
            const float v0 = fmaxf(a[0] + bia0, 0.f);
            const float v1 = fmaxf(a[1] + bia0, 0.f);
            const float v2 = fmaxf(a[2] + bia1, 0.f);
            const float v3 = fmaxf(a[3] + bia1, 0.f);
            *(uint32_t*)(smc + MH(0) + o * 144 + n * 2)       = bfhi2(v0, v1);
            *(uint32_t*)(smc + MH(1) + o * 144 + n * 2)       = bflo2(v0, v1);
            *(uint32_t*)(smc + MH(0) + (o + 8) * 144 + n * 2) = bfhi2(v2, v3);
            *(uint32_t*)(smc + MH(1) + (o + 8) * 144 + n * 2) = bflo2(v2, v3);
        }
    }
    FILLW2(1);
    __syncthreads();

    // ---------- GEMM2 ----------
    const int ow2 = w >> 1;   // 32 o per warp
    float acc2[8][4];
    #pragma unroll
    for (int i = 0; i < 8; i++)
        #pragma unroll
        for (int j = 0; j < 4; j++) acc2[i][j] = 0.f;

    for (int kc = 0; kc < 8; kc++) {
        const int buf = kc & 1;
        #pragma unroll
        for (int kk = 0; kk < 2; kk++) {
            uint32_t wh[2][4], wl[2][4];
            #pragma unroll
            for (int mi = 0; mi < 2; mi++) {
                const uint32_t o = ow2 * 32 + mi * 16 + (lane & 15);
                const uint32_t off = PR(o) + kk * 32 + (lane >> 4) * 16;
                ldsm4(wh[mi], sb + MW2(buf, 0) + off);
                ldsm4(wl[mi], sb + MW2(buf, 1) + off);
            }
            uint32_t hh[4][2], hl[4][2];
            #pragma unroll
            for (int np = 0; np < 2; np++) {
                const uint32_t row  = kc * 32 + kk * 16 + ((lane >> 3) & 1) * 8 + (lane & 7);
                const uint32_t colb = (nw * 32 + np * 16) * 2 + (lane >> 4) * 16;
                uint32_t r[4];
                ldsm4t(r, sb + MH(0) + row * 144 + colb);
                hh[np * 2][0] = r[0]; hh[np * 2][1] = r[1];
                hh[np * 2 + 1][0] = r[2]; hh[np * 2 + 1][1] = r[3];
                ldsm4t(r, sb + MH(1) + row * 144 + colb);
                hl[np * 2][0] = r[0]; hl[np * 2][1] = r[1];
                hl[np * 2 + 1][0] = r[2]; hl[np * 2 + 1][1] = r[3];
            }
            #pragma unroll
            for (int mi = 0; mi < 2; mi++)
                #pragma unroll
                for (int ni = 0; ni < 4; ni++) {
                    mma_bf16(acc2[mi * 4 + ni], wh[mi], hh[ni]);
                    mma_bf16(acc2[mi * 4 + ni], wh[mi], hl[ni]);
                    mma_bf16(acc2[mi * 4 + ni], wl[mi], hh[ni]);
                }
        }
        if (kc < 6) FILLW2(kc + 2);
        __syncthreads();
    }
    #undef FILLW2

    // ---------- output ----------
    #pragma unroll
    for (int mi = 0; mi < 2; mi++) {
        const int o = ow2 * 32 + mi * 16 + (lane >> 2);
        const float bia0 = s_b2[o], bia1 = s_b2[o + 8];
        #pragma unroll
        for (int ni = 0; ni < 4; ni++) {
            const int n = n0 + nw * 32 + ni * 8 + (lane & 3) * 2;
            const float* a = acc2[mi * 4 + ni];
            float2 v0, v1;
            v0.x = fmaxf(a[0] + bia0, 0.f);
            v0.y = fmaxf(a[1] + bia0, 0.f);
            v1.x = fmaxf(a[2] + bia1, 0.f);
            v1.y = fmaxf(a[3] + bia1, 0.f);
            *(float2*)&out[((size_t)b * H2n + o) * Nn + n]     = v0;
            *(float2*)&out[((size_t)b * H2n + o + 8) * Nn + n] = v1;
        }
    }
}

extern "C" void kernel_launch(void* const* d_in, const int* in_sizes, int n_in,
                              void* d_out, int out_size)
{
    const float* xyz1 = (const float*)d_in[0];
    const float* xyz2 = (const float*)d_in[1];
    const float* p1   = (const float*)d_in[2];
    const float* p2   = (const float*)d_in[3];
    const float* W1   = (const float*)d_in[4];
    const float* b1   = (const float*)d_in[5];
    const float* W2   = (const float*)d_in[6];
    const float* b2   = (const float*)d_in[7];
    float* out = (float*)d_out;

    cudaFuncSetAttribute(interp_tc, cudaFuncAttributeMaxDynamicSharedMemorySize, ISMB);
    cudaFuncSetAttribute(mlp_tc,    cudaFuncAttributeMaxDynamicSharedMemorySize, MSMB);

    dim3 grid(Nn / 64, Bn);
    interp_tc<<<grid, 256, ISMB>>>(xyz1, xyz2, p2);
    mlp_tc<<<grid, 256, MSMB>>>(p1, W1, b1, W2, b2, out);
}

// round 7
// speedup vs baseline: 1.2736x; 1.2736x over previous
#include <cuda_runtime.h>
#include <cuda_bf16.h>
#include <cstdint>

// Problem constants
#define Bn   16
#define Nn   4096
#define Mn   1024
#define C1n  128
#define C2n  256
#define CINn 384
#define H1n  256
#define H2n  128

// ---------------- helpers ----------------
__device__ __forceinline__ uint32_t smem_u32(const void* p) {
    uint32_t a;
    asm("{ .reg .u64 t; cvta.to.shared.u64 t, %1; cvt.u32.u64 %0, t; }" : "=r"(a) : "l"(p));
    return a;
}
__device__ __forceinline__ void ldsm4(uint32_t* r, uint32_t addr) {
    asm volatile("ldmatrix.sync.aligned.m8n8.x4.shared.b16 {%0,%1,%2,%3}, [%4];"
        : "=r"(r[0]), "=r"(r[1]), "=r"(r[2]), "=r"(r[3]) : "r"(addr));
}
__device__ __forceinline__ void ldsm4t(uint32_t* r, uint32_t addr) {
    asm volatile("ldmatrix.sync.aligned.m8n8.x4.trans.shared.b16 {%0,%1,%2,%3}, [%4];"
        : "=r"(r[0]), "=r"(r[1]), "=r"(r[2]), "=r"(r[3]) : "r"(addr));
}
__device__ __forceinline__ void mma_bf16(float* d, const uint32_t* a, const uint32_t* b) {
    asm volatile("mma.sync.aligned.m16n8k16.row.col.f32.bf16.bf16.f32 "
        "{%0,%1,%2,%3}, {%4,%5,%6,%7}, {%8,%9}, {%0,%1,%2,%3};"
        : "+f"(d[0]), "+f"(d[1]), "+f"(d[2]), "+f"(d[3])
        : "r"(a[0]), "r"(a[1]), "r"(a[2]), "r"(a[3]), "r"(b[0]), "r"(b[1]));
}
__device__ __forceinline__ uint32_t bfhi2(float a, float b) {
    return __byte_perm(__float_as_uint(a), __float_as_uint(b), 0x7632);
}
__device__ __forceinline__ uint32_t bflo2(float a, float b) {
    const float la = a - __uint_as_float(__float_as_uint(a) & 0xFFFF0000u);
    const float lb = b - __uint_as_float(__float_as_uint(b) & 0xFFFF0000u);
    __nv_bfloat162 p = __floats2bfloat162_rn(la, lb);
    return *(uint32_t*)&p;
}
#define CP16(dst, src) asm volatile("cp.async.cg.shared.global [%0], [%1], 16;" :: "r"(dst), "l"(src))
#define CPCOMMIT()     asm volatile("cp.async.commit_group;" ::: "memory")
#define CPWAIT(n)      asm volatile("cp.async.wait_group %0;" :: "n"(n) : "memory")

// device scratch
__device__ float    g_interp[(size_t)Bn * C2n * Nn];
__device__ uint16_t g_p2h[(size_t)Bn * C2n * Mn];
__device__ uint16_t g_p2l[(size_t)Bn * C2n * Mn];

// prep: split p2 fp32 -> bf16 hi/lo
__global__ void split_p2(const float* __restrict__ src)
{
    const size_t i = (size_t)blockIdx.x * 256 + threadIdx.x;   // float4 index
    const float4 v = ((const float4*)src)[i];
    uint2 h, l;
    h.x = bfhi2(v.x, v.y); h.y = bfhi2(v.z, v.w);
    l.x = bflo2(v.x, v.y); l.y = bflo2(v.z, v.w);
    ((uint2*)g_p2h)[i] = h;
    ((uint2*)g_p2l)[i] = l;
}

// paired-row address: two logical 64B rows per 144B physical row (conflict-free ldsm)
#define PR(r) (((r) >> 1) * 144 + ((r) & 1) * 64)

// ================= Kernel 1: interpolation via mma.sync =================
// CTA: 64 n x 256 c.  K = M = 1024 in 32-chunks, double-buffered, occ 2.
// A [64n][32k] pitch 80 (SIMT fill); B [256c][32k] paired rows (cp.async).
#define IA(buf, part)  ((buf) * 10240 + (part) * 5120)
#define IB(buf, part)  (20480 + (buf) * 36864 + (part) * 18432)
#define IOFF_X2  94208              // SoA: x[1024], y[1024], z[1024]
#define IOFF_DS  106496
#define IOFF_DEN 107520
#define ISMB     107776

__global__ __launch_bounds__(256, 2)
void interp_tc(const float* __restrict__ xyz1,
               const float* __restrict__ xyz2)
{
    extern __shared__ char smc[];
    const uint32_t sb = smem_u32(smc);
    float* s_x2x = (float*)(smc + IOFF_X2);
    float* s_x2y = s_x2x + Mn;
    float* s_x2z = s_x2x + 2 * Mn;
    float* s_ds  = (float*)(smc + IOFF_DS);
    float* s_den = (float*)(smc + IOFF_DEN);

    const int tid = threadIdx.x, w = tid >> 5, lane = tid & 31;
    const int b = blockIdx.y, n0 = blockIdx.x * 64;

    // xyz2 -> SoA smem
    for (int m = tid; m < Mn; m += 256) {
        const float3 v = ((const float3*)(xyz2 + (size_t)b * Mn * 3))[m];
        s_x2x[m] = v.x; s_x2y[m] = v.y; s_x2z[m] = v.z;
    }
    __syncthreads();

    const int nf = tid & 63;        // point this thread generates weights for
    const int g  = tid >> 6;        // 8-m group within 32-chunk
    const float px = xyz1[((size_t)b * Nn + n0 + nf) * 3 + 0];
    const float py = xyz1[((size_t)b * Nn + n0 + nf) * 3 + 1];
    const float pz = xyz1[((size_t)b * Nn + n0 + nf) * 3 + 2];
    float dsum = 0.f;

    const int mw = w & 1, cw = w >> 1;   // warp tile: 32 n x 64 c
    float acc[16][4];
    #pragma unroll
    for (int i = 0; i < 16; i++)
        #pragma unroll
        for (int j = 0; j < 4; j++) acc[i][j] = 0.f;

    const size_t p2base = (size_t)b * C2n * Mn;

    // A fill: SIMT rsqrt weights hi/lo (8 m per thread per chunk)
    #define FILLA(ch) do {                                                         \
        const int _buf = (ch) & 1, _mb = (ch) * 32 + g * 8;                        \
        const float4 xa = *(const float4*)&s_x2x[_mb];                             \
        const float4 xbv = *(const float4*)&s_x2x[_mb + 4];                        \
        const float4 ya = *(const float4*)&s_x2y[_mb];                             \
        const float4 yb = *(const float4*)&s_x2y[_mb + 4];                         \
        const float4 za = *(const float4*)&s_x2z[_mb];                             \
        const float4 zb = *(const float4*)&s_x2z[_mb + 4];                         \
        const float xs[8] = {xa.x, xa.y, xa.z, xa.w, xbv.x, xbv.y, xbv.z, xbv.w};  \
        const float ys[8] = {ya.x, ya.y, ya.z, ya.w, yb.x, yb.y, yb.z, yb.w};      \
        const float zs[8] = {za.x, za.y, za.z, za.w, zb.x, zb.y, zb.z, zb.w};      \
        float iv[8];                                                               \
        _Pragma("unroll")                                                          \
        for (int t = 0; t < 8; t++) {                                              \
            const float dx = px - xs[t];                                           \
            const float dy = py - ys[t];                                           \
            const float dz = pz - zs[t];                                           \
            const float d2 = fmaf(dx, dx, fmaf(dy, dy, fmaf(dz, dz, 1e-16f)));     \
            iv[t] = rsqrtf(d2);                                                    \
            dsum += iv[t];                                                         \
        }                                                                          \
        uint4 hv, lv;                                                              \
        hv.x = bfhi2(iv[0], iv[1]); hv.y = bfhi2(iv[2], iv[3]);                    \
        hv.z = bfhi2(iv[4], iv[5]); hv.w = bfhi2(iv[6], iv[7]);                    \
        lv.x = bflo2(iv[0], iv[1]); lv.y = bflo2(iv[2], iv[3]);                    \
        lv.z = bflo2(iv[4], iv[5]); lv.w = bflo2(iv[6], iv[7]);                    \
        *(uint4*)(smc + IA(_buf, 0) + nf * 80 + g * 16) = hv;                      \
        *(uint4*)(smc + IA(_buf, 1) + nf * 80 + g * 16) = lv;                      \
    } while (0)

    // B fill: cp.async pre-split p2 chunk, 8 x 16B per thread
    #define FILLB(ch) do {                                                         \
        const int _buf = (ch) & 1, _m0 = (ch) * 32;                                \
        _Pragma("unroll")                                                          \
        for (int it = 0; it < 8; it++) {                                           \
            const int u = tid + it * 256;                                          \
            const int part = u >> 10;                                              \
            const int v = u & 1023, c = v >> 2, s = v & 3;                         \
            const uint32_t dst = sb + IB(_buf, part) + PR(c) + s * 16;             \
            const uint16_t* srcp = part ? g_p2l : g_p2h;                           \
            CP16(dst, srcp + p2base + (size_t)c * Mn + _m0 + s * 8);               \
        }                                                                          \
        CPCOMMIT();                                                                \
    } while (0)

    FILLA(0);
    FILLB(0);

    for (int ch = 0; ch < 32; ch++) {
        const int buf = ch & 1;
        CPWAIT(0);
        __syncthreads();
        if (ch < 31) { FILLB(ch + 1); FILLA(ch + 1); }

        #pragma unroll
        for (int kk = 0; kk < 2; kk++) {
            uint32_t ah[2][4], al[2][4];
            #pragma unroll
            for (int mt = 0; mt < 2; mt++) {
                const uint32_t row = mw * 32 + mt * 16 + (lane & 15);
                const uint32_t off = row * 80 + kk * 32 + (lane >> 4) * 16;
                ldsm4(ah[mt], sb + IA(buf, 0) + off);
                ldsm4(al[mt], sb + IA(buf, 1) + off);
            }
            #pragma unroll
            for (int cp = 0; cp < 4; cp++) {
                const uint32_t c = cw * 64 + cp * 16 + (lane >> 4) * 8 + (lane & 7);
                const uint32_t off = PR(c) + kk * 32 + ((lane >> 3) & 1) * 16;
                uint32_t rh[4], rl[4];
                ldsm4(rh, sb + IB(buf, 0) + off);
                ldsm4(rl, sb + IB(buf, 1) + off);
                #pragma unroll
                for (int mt = 0; mt < 2; mt++) {
                    mma_bf16(acc[mt * 8 + cp * 2],     ah[mt], rh);
                    mma_bf16(acc[mt * 8 + cp * 2 + 1], ah[mt], rh + 2);
                    mma_bf16(acc[mt * 8 + cp * 2],     ah[mt], rl);
                    mma_bf16(acc[mt * 8 + cp * 2 + 1], ah[mt], rl + 2);
                    mma_bf16(acc[mt * 8 + cp * 2],     al[mt], rh);
                    mma_bf16(acc[mt * 8 + cp * 2 + 1], al[mt], rh + 2);
                }
            }
        }
    }
    #undef FILLA
    #undef FILLB

    // denominator
    __syncthreads();
    s_ds[tid] = dsum;
    __syncthreads();
    if (tid < 64)
        s_den[tid] = 1.0f / (s_ds[tid] + s_ds[tid + 64] + s_ds[tid + 128] + s_ds[tid + 192]);
    __syncthreads();

    // epilogue: scale and store
    #pragma unroll
    for (int mt = 0; mt < 2; mt++) {
        const int nl = mw * 32 + mt * 16 + (lane >> 2);
        const float i0 = s_den[nl], i1 = s_den[nl + 8];
        #pragma unroll
        for (int ct = 0; ct < 8; ct++) {
            const int c = cw * 64 + ct * 8 + (lane & 3) * 2;
            float* d0 = &g_interp[((size_t)b * C2n + c) * Nn + n0];
            float* d1 = &g_interp[((size_t)b * C2n + c + 1) * Nn + n0];
            const float* a = acc[mt * 8 + ct];
            d0[nl]     = a[0] * i0;
            d1[nl]     = a[1] * i0;
            d0[nl + 8] = a[2] * i1;
            d1[nl + 8] = a[3] * i1;
        }
    }
}

// ================= Kernel 2: fused 2-layer MLP via mma.sync =================
// CTA: 64 n. GEMM1: 256o x 64n x K384 (32-chunks); GEMM2: 128o x 64n x K256.
#define MW(buf, part)   ((buf) * 36864 + (part) * 18432)          // W1 chunk [256o][32k] paired
#define MH(part)        ((part) * 36864)                           // h [256k][64n] (overlays MW)
#define MX(buf, part)   (73728 + (buf) * 9216 + (part) * 4608)     // x chunk [32k][64n]
#define MW2(buf, part)  (73728 + (buf) * 18432 + (part) * 9216)    // W2 chunk [128o][32k] paired
#define MOFF_B1  110592
#define MOFF_B2  111616
#define MSMB     112128

__global__ __launch_bounds__(256, 2)
void mlp_tc(const float* __restrict__ p1,
            const float* __restrict__ W1,
            const float* __restrict__ b1,
            const float* __restrict__ W2,
            const float* __restrict__ b2,
            float* __restrict__ out)
{
    extern __shared__ char smc[];
    const uint32_t sb = smem_u32(smc);
    float* s_b1 = (float*)(smc + MOFF_B1);
    float* s_b2 = (float*)(smc + MOFF_B2);

    const int tid = threadIdx.x, w = tid >> 5, lane = tid & 31;
    const int b = blockIdx.y, n0 = blockIdx.x * 64;

    s_b1[tid] = b1[tid];
    if (tid < H2n) s_b2[tid] = b2[tid];

    const int ow = w >> 1, nw = w & 1;   // GEMM1 warp: 64 o x 32 n

    #define FILLW1(kc) do {                                                         \
        const int _buf = (kc) & 1;                                                  \
        _Pragma("unroll")                                                           \
        for (int it = 0; it < 8; it++) {                                            \
            const int u = tid + it * 256;                                           \
            const int o = u >> 3, q = u & 7;                                        \
            const float4 v = *(const float4*)&W1[(size_t)o * CINn + (kc) * 32 + q * 4]; \
            uint2 hv, lv;                                                           \
            hv.x = bfhi2(v.x, v.y); hv.y = bfhi2(v.z, v.w);                         \
            lv.x = bflo2(v.x, v.y); lv.y = bflo2(v.z, v.w);                         \
            *(uint2*)(smc + MW(_buf, 0) + PR(o) + q * 8) = hv;                      \
            *(uint2*)(smc + MW(_buf, 1) + PR(o) + q * 8) = lv;                      \
        }                                                                           \
    } while (0)

    #define FILLX(kc) do {                                                          \
        const int _buf = (kc) & 1;                                                  \
        _Pragma("unroll")                                                           \
        for (int it = 0; it < 2; it++) {                                            \
            const int u = tid + it * 256;                                           \
            const int k = u >> 4, q = u & 15;                                       \
            const int c = (kc) * 32 + k;                                            \
            const float* src = (c < C1n)                                            \
                ? &p1[((size_t)b * C1n + c) * Nn]                                   \
                : &g_interp[((size_t)b * C2n + (c - C1n)) * Nn];                    \
            const float4 v = *(const float4*)&src[n0 + q * 4];                      \
            uint2 hv, lv;                                                           \
            hv.x = bfhi2(v.x, v.y); hv.y = bfhi2(v.z, v.w);                         \
            lv.x = bflo2(v.x, v.y); lv.y = bflo2(v.z, v.w);                         \
            *(uint2*)(smc + MX(_buf, 0) + k * 144 + q * 8) = hv;                    \
            *(uint2*)(smc + MX(_buf, 1) + k * 144 + q * 8) = lv;                    \
        }                                                                           \
    } while (0)

    float acc1[16][4];
    #pragma unroll
    for (int i = 0; i < 16; i++)
        #pragma unroll
        for (int j = 0; j < 4; j++) acc1[i][j] = 0.f;

    FILLW1(0); FILLX(0);
    __syncthreads();

    for (int kc = 0; kc < 12; kc++) {
        const int buf = kc & 1;
        #pragma unroll
        for (int kk = 0; kk < 2; kk++) {
            uint32_t wh[4][4], wl[4][4];
            #pragma unroll
            for (int mi = 0; mi < 4; mi++) {
                const uint32_t o = ow * 64 + mi * 16 + (lane & 15);
                const uint32_t off = PR(o) + kk * 32 + (lane >> 4) * 16;
                ldsm4(wh[mi], sb + MW(buf, 0) + off);
                ldsm4(wl[mi], sb + MW(buf, 1) + off);
            }
            uint32_t xh[4][2], xl[4][2];
            #pragma unroll
            for (int np = 0; np < 2; np++) {
                const uint32_t row  = kk * 16 + ((lane >> 3) & 1) * 8 + (lane & 7);
                const uint32_t colb = (nw * 32 + np * 16) * 2 + (lane >> 4) * 16;
                uint32_t r[4];
                ldsm4t(r, sb + MX(buf, 0) + row * 144 + colb);
                xh[np * 2][0] = r[0]; xh[np * 2][1] = r[1];
                xh[np * 2 + 1][0] = r[2]; xh[np * 2 + 1][1] = r[3];
                ldsm4t(r, sb + MX(buf, 1) + row * 144 + colb);
                xl[np * 2][0] = r[0]; xl[np * 2][1] = r[1];
                xl[np * 2 + 1][0] = r[2]; xl[np * 2 + 1][1] = r[3];
            }
            #pragma unroll
            for (int mi = 0; mi < 4; mi++)
                #pragma unroll
                for (int ni = 0; ni < 4; ni++) {
                    mma_bf16(acc1[mi * 4 + ni], wh[mi], xh[ni]);
                    mma_bf16(acc1[mi * 4 + ni], wh[mi], xl[ni]);
                    mma_bf16(acc1[mi * 4 + ni], wl[mi], xh[ni]);
                }
        }
        if (kc < 11) { FILLW1(kc + 1); FILLX(kc + 1); }
        __syncthreads();
    }
    #undef FILLW1
    #undef FILLX

    #define FILLW2(kc) do {                                                         \
        const int _buf = (kc) & 1;                                                  \
        _Pragma("unroll")                                                           \
        for (int it = 0; it < 4; it++) {                                            \
            const int u = tid + it * 256;                                           \
            const int o = u >> 3, q = u & 7;                                        \
            const float4 v = *(const float4*)&W2[(size_t)o * H1n + (kc) * 32 + q * 4]; \
            uint2 hv, lv;                                                           \
            hv.x = bfhi2(v.x, v.y); hv.y = bfhi2(v.z, v.w);                         \
            lv.x = bflo2(v.x, v.y); lv.y = bflo2(v.z, v.w);                         \
            *(uint2*)(smc + MW2(_buf, 0) + PR(o) + q * 8) = hv;                     \
            *(uint2*)(smc + MW2(_buf, 1) + PR(o) + q * 8) = lv;                     \
        }                                                                           \
    } while (0)

    // W1/x regions fully read; repurpose for W2 + h
    FILLW2(0);

    // GEMM1 epilogue: relu + bias -> s_h [256 k-rows][64 n], hi/lo (overlays MW)
    #pragma unroll
    for (int mi = 0; mi < 4; mi++) {
        const int o = ow * 64 + mi * 16 + (lane >> 2);
        const float bia0 = s_b1[o], bia1 = s_b1[o + 8];
        #pragma unroll
        for (int ni = 0; ni < 4; ni++) {
            const int n = nw * 32 + ni * 8 + (lane & 3) * 2;
            const float* a = acc1[mi * 4 + ni];
            const float v0 = fmaxf(a[0] + bia0, 0.f);
            const float v1 = fmaxf(a[1] + bia0, 0.f);
            const float v2 = fmaxf(a[2] + bia1, 0.f);
            const float v3 = fmaxf(a[3] + bia1, 0.f);
            *(uint32_t*)(smc + MH(0) + o * 144 + n * 2)       = bfhi2(v0, v1);
            *(uint32_t*)(smc + MH(1) + o * 144 + n * 2)       = bflo2(v0, v1);
            *(uint32_t*)(smc + MH(0) + (o + 8) * 144 + n * 2) = bfhi2(v2, v3);
            *(uint32_t*)(smc + MH(1) + (o + 8) * 144 + n * 2) = bflo2(v2, v3);
        }
    }
    __syncthreads();

    // ---------- GEMM2 (distance-1 double buffer, race-free) ----------
    const int ow2 = w >> 1;   // 32 o per warp
    float acc2[8][4];
    #pragma unroll
    for (int i = 0; i < 8; i++)
        #pragma unroll
        for (int j = 0; j < 4; j++) acc2[i][j] = 0.f;

    for (int kc = 0; kc < 8; kc++) {
        const int buf = kc & 1;
        #pragma unroll
        for (int kk = 0; kk < 2; kk++) {
            uint32_t wh[2][4], wl[2][4];
            #pragma unroll
            for (int mi = 0; mi < 2; mi++) {
                const uint32_t o = ow2 * 32 + mi * 16 + (lane & 15);
                const uint32_t off = PR(o) + kk * 32 + (lane >> 4) * 16;
                ldsm4(wh[mi], sb + MW2(buf, 0) + off);
                ldsm4(wl[mi], sb + MW2(buf, 1) + off);
            }
            uint32_t hh[4][2], hl[4][2];
            #pragma unroll
            for (int np = 0; np < 2; np++) {
                const uint32_t row  = kc * 32 + kk * 16 + ((lane >> 3) & 1) * 8 + (lane & 7);
                const uint32_t colb = (nw * 32 + np * 16) * 2 + (lane >> 4) * 16;
                uint32_t r[4];
                ldsm4t(r, sb + MH(0) + row * 144 + colb);
                hh[np * 2][0] = r[0]; hh[np * 2][1] = r[1];
                hh[np * 2 + 1][0] = r[2]; hh[np * 2 + 1][1] = r[3];
                ldsm4t(r, sb + MH(1) + row * 144 + colb);
                hl[np * 2][0] = r[0]; hl[np * 2][1] = r[1];
                hl[np * 2 + 1][0] = r[2]; hl[np * 2 + 1][1] = r[3];
            }
            #pragma unroll
            for (int mi = 0; mi < 2; mi++)
                #pragma unroll
                for (int ni = 0; ni < 4; ni++) {
                    mma_bf16(acc2[mi * 4 + ni], wh[mi], hh[ni]);
                    mma_bf16(acc2[mi * 4 + ni], wh[mi], hl[ni]);
                    mma_bf16(acc2[mi * 4 + ni], wl[mi], hh[ni]);
                }
        }
        if (kc < 7) FILLW2(kc + 1);   // writes OTHER buffer — safe
        __syncthreads();
    }
    #undef FILLW2

    // ---------- output ----------
    #pragma unroll
    for (int mi = 0; mi < 2; mi++) {
        const int o = ow2 * 32 + mi * 16 + (lane >> 2);
        const float bia0 = s_b2[o], bia1 = s_b2[o + 8];
        #pragma unroll
        for (int ni = 0; ni < 4; ni++) {
            const int n = n0 + nw * 32 + ni * 8 + (lane & 3) * 2;
            const float* a = acc2[mi * 4 + ni];
            float2 v0, v1;
            v0.x = fmaxf(a[0] + bia0, 0.f);
            v0.y = fmaxf(a[1] + bia0, 0.f);
            v1.x = fmaxf(a[2] + bia1, 0.f);
            v1.y = fmaxf(a[3] + bia1, 0.f);
            *(float2*)&out[((size_t)b * H2n + o) * Nn + n]     = v0;
            *(float2*)&out[((size_t)b * H2n + o + 8) * Nn + n] = v1;
        }
    }
}

extern "C" void kernel_launch(void* const* d_in, const int* in_sizes, int n_in,
                              void* d_out, int out_size)
{
    const float* xyz1 = (const float*)d_in[0];
    const float* xyz2 = (const float*)d_in[1];
    const float* p1   = (const float*)d_in[2];
    const float* p2   = (const float*)d_in[3];
    const float* W1   = (const float*)d_in[4];
    const float* b1   = (const float*)d_in[5];
    const float* W2   = (const float*)d_in[6];
    const float* b2   = (const float*)d_in[7];
    float* out = (float*)d_out;

    cudaFuncSetAttribute(interp_tc, cudaFuncAttributeMaxDynamicSharedMemorySize, ISMB);
    cudaFuncSetAttribute(mlp_tc,    cudaFuncAttributeMaxDynamicSharedMemorySize, MSMB);

    split_p2<<<(Bn * C2n * Mn / 4) / 256, 256>>>(p2);
    dim3 grid(Nn / 64, Bn);
    interp_tc<<<grid, 256, ISMB>>>(xyz1, xyz2);
    mlp_tc<<<grid, 256, MSMB>>>(p1, W1, b1, W2, b2, out);
}